// round 8
// baseline (speedup 1.0000x reference)
#include <cuda_runtime.h>
#include <cuda_bf16.h>
#include <cstdint>

#define NTHR    256
#define IPT     256                  // items per tile (1 item = 4 points = 48B)
#define TILE_B  (IPT * 48)           // 12288 bytes per tile
#define IPB     (2 * IPT)            // 512 items per block, two tiles
#define MAXBLK  4096

// Per-block partials + completion ticket (module-scope device memory; no allocs).
__device__ float g_sum[MAXBLK];
__device__ int   g_cnt[MAXBLK];
__device__ float g_max[MAXBLK];
__device__ unsigned int g_done = 0;

__device__ __forceinline__ void point_acc(float x, float y, float z,
                                          float& acc_sum, int& acc_cnt, float& acc_max) {
    // Fold into positive octant: octahedron |x|+|y|+|z| <= 1 is sign-symmetric.
    float qx = fabsf(x), qy = fabsf(y), qz = fabsf(z);
    float s   = qx + qy + qz;
    float x2  = x * x, y2 = y * y, z2 = z * z;
    float dot = fmaf(x, x, fmaf(y, y, z * z));

    const float C = 0.57735026918962576f;           // fp32(1/sqrt(3))
    bool inside = (s * C - C) <= 1e-8f;             // same arithmetic as reference

    float mx  = fmaxf(qx, fmaxf(qy, qz));
    float mn  = fminf(qx, fminf(qy, qz));
    float mn2 = fminf(x2, fminf(y2, z2));

    float d2v = fmaf(-2.0f, mx, dot + 1.0f);        // nearest-vertex dist^2

    if (inside) {
        acc_sum += d2v;
        acc_cnt += 1;
    } else {
        // Exact distance^2 to simplex {q>=0, sum=1}: sorted threshold cascade.
        float t1      = s - 1.0f;
        float face_sq = (t1 * (1.0f / 3.0f)) * t1;
        bool  face_ok = (3.0f * mn >= t1);

        float tau2 = fmaf(0.5f, s - mn, -0.5f);
        float e    = fmaf(tau2 + tau2, tau2, mn2);
        bool  edge_ok = fmaf(-2.0f, mx, s + 1.0f) >= mn;

        float sq = edge_ok ? e : d2v;
        sq = face_ok ? face_sq : sq;
        acc_max = fmaxf(acc_max, sq);
    }
}

__device__ __forceinline__ uint32_t smem_u32(const void* p) {
    uint32_t a;
    asm("{ .reg .u64 t; cvta.to.shared.u64 t, %1; cvt.u32.u64 %0, t; }" : "=r"(a) : "l"(p));
    return a;
}

__device__ __forceinline__ void mbar_wait0(uint32_t mbar_a) {
    uint32_t done;
    asm volatile(
        "{\n\t.reg .pred p;\n\t"
        "mbarrier.try_wait.parity.acquire.cta.shared::cta.b64 p, [%1], 0;\n\t"
        "selp.b32 %0, 1, 0, p;\n\t}"
        : "=r"(done) : "r"(mbar_a) : "memory");
    while (!done) {
        asm volatile(
            "{\n\t.reg .pred p;\n\t"
            "mbarrier.try_wait.parity.acquire.cta.shared::cta.b64 p, [%1], 0, 0x989680;\n\t"
            "selp.b32 %0, 1, 0, p;\n\t}"
            : "=r"(done) : "r"(mbar_a) : "memory");
    }
}

__device__ __forceinline__ void item4_acc(float4 f0, float4 f1, float4 f2,
                                          float& acc_sum, int& acc_cnt, float& acc_max) {
    point_acc(f0.x, f0.y, f0.z, acc_sum, acc_cnt, acc_max);
    point_acc(f0.w, f1.x, f1.y, acc_sum, acc_cnt, acc_max);
    point_acc(f1.z, f1.w, f2.x, acc_sum, acc_cnt, acc_max);
    point_acc(f2.y, f2.z, f2.w, acc_sum, acc_cnt, acc_max);
}

// ---- Single fused kernel: two 12KB TMA tiles per block + ticket-based final reduce ----
__global__ void __launch_bounds__(NTHR)
pbl_kernel(const char* __restrict__ pts_bytes, const float* __restrict__ pts,
           float* __restrict__ out, int n_items, int n_points, int n_blocks) {
    __shared__ alignas(128) float4 tile0[TILE_B / 16];
    __shared__ alignas(128) float4 tile1[TILE_B / 16];
    __shared__ alignas(8)  uint64_t mbar0, mbar1;
    __shared__ float s_sum[NTHR / 32];
    __shared__ int   s_cnt[NTHR / 32];
    __shared__ float s_max[NTHR / 32];
    __shared__ bool  s_is_last;

    const int tid  = threadIdx.x;
    const int lane = tid & 31;
    const int wid  = tid >> 5;

    const int first_item = blockIdx.x * IPB;
    const int rem        = n_items - first_item;               // may be <= 0
    const int items0     = max(0, min(IPT, rem));
    const int items1     = max(0, min(IPT, rem - IPT));
    const uint32_t bytes0 = (uint32_t)items0 * 48u;
    const uint32_t bytes1 = (uint32_t)items1 * 48u;

    const uint32_t mb0 = smem_u32(&mbar0);
    const uint32_t mb1 = smem_u32(&mbar1);
    const uint32_t d0  = smem_u32(tile0);
    const uint32_t d1  = smem_u32(tile1);

    if (tid == 0) {
        asm volatile("mbarrier.init.shared.b64 [%0], %1;" :: "r"(mb0), "r"(1u) : "memory");
        asm volatile("mbarrier.init.shared.b64 [%0], %1;" :: "r"(mb1), "r"(1u) : "memory");
    }
    __syncthreads();

    if (tid == 0) {
        const char* src = pts_bytes + (size_t)first_item * 48u;
        asm volatile("mbarrier.arrive.expect_tx.shared.b64 _, [%0], %1;"
                     :: "r"(mb0), "r"(bytes0) : "memory");
        if (bytes0 > 0)
            asm volatile(
                "cp.async.bulk.shared::cta.global.mbarrier::complete_tx::bytes [%0], [%1], %2, [%3];"
                :: "r"(d0), "l"(src), "r"(bytes0), "r"(mb0) : "memory");
        asm volatile("mbarrier.arrive.expect_tx.shared.b64 _, [%0], %1;"
                     :: "r"(mb1), "r"(bytes1) : "memory");
        if (bytes1 > 0)
            asm volatile(
                "cp.async.bulk.shared::cta.global.mbarrier::complete_tx::bytes [%0], [%1], %2, [%3];"
                :: "r"(d1), "l"(src + TILE_B), "r"(bytes1), "r"(mb1) : "memory");
    }

    float acc_sum = 0.0f;
    int   acc_cnt = 0;
    float acc_max = 0.0f;

    // tile 0
    mbar_wait0(mb0);
    if (tid < items0) {
        float4 f0 = tile0[3 * tid + 0];     // 48B-stride LDS.128, conflict-free
        float4 f1 = tile0[3 * tid + 1];
        float4 f2 = tile0[3 * tid + 2];
        item4_acc(f0, f1, f2, acc_sum, acc_cnt, acc_max);
    }
    // tile 1 (DRAM service overlapped with tile-0 compute)
    mbar_wait0(mb1);
    if (tid < items1) {
        float4 f0 = tile1[3 * tid + 0];
        float4 f1 = tile1[3 * tid + 1];
        float4 f2 = tile1[3 * tid + 2];
        item4_acc(f0, f1, f2, acc_sum, acc_cnt, acc_max);
    }

    // warp reduce
    #pragma unroll
    for (int o = 16; o > 0; o >>= 1) {
        acc_sum += __shfl_down_sync(0xffffffffu, acc_sum, o);
        acc_max  = fmaxf(acc_max, __shfl_down_sync(0xffffffffu, acc_max, o));
    }
    acc_cnt = __reduce_add_sync(0xffffffffu, acc_cnt);

    if (lane == 0) { s_sum[wid] = acc_sum; s_cnt[wid] = acc_cnt; s_max[wid] = acc_max; }
    __syncthreads();

    if (tid == 0) {
        float bs = 0.0f; int bc = 0; float bm = 0.0f;
        #pragma unroll
        for (int i = 0; i < NTHR / 32; i++) {
            bs += s_sum[i]; bc += s_cnt[i]; bm = fmaxf(bm, s_max[i]);
        }
        g_sum[blockIdx.x] = bs;
        g_cnt[blockIdx.x] = bc;
        g_max[blockIdx.x] = bm;
        __threadfence();
        unsigned int ticket = atomicAdd(&g_done, 1u);
        s_is_last = (ticket == (unsigned int)(n_blocks - 1));
    }
    __syncthreads();

    if (s_is_last) {
        __threadfence();  // acquire: all blocks' partials visible (L2-resident)
        float fs = 0.0f; int fc = 0; float fm = 0.0f;
        for (int i = tid; i < n_blocks; i += NTHR) {
            fs += g_sum[i]; fc += g_cnt[i]; fm = fmaxf(fm, g_max[i]);
        }
        #pragma unroll
        for (int o = 16; o > 0; o >>= 1) {
            fs += __shfl_down_sync(0xffffffffu, fs, o);
            fm  = fmaxf(fm, __shfl_down_sync(0xffffffffu, fm, o));
        }
        fc = __reduce_add_sync(0xffffffffu, fc);
        if (lane == 0) { s_sum[wid] = fs; s_cnt[wid] = fc; s_max[wid] = fm; }
        __syncthreads();
        if (tid == 0) {
            float fs2 = 0.0f; int fc2 = 0; float fm2 = 0.0f;
            #pragma unroll
            for (int i = 0; i < NTHR / 32; i++) {
                fs2 += s_sum[i]; fc2 += s_cnt[i]; fm2 = fmaxf(fm2, s_max[i]);
            }
            // scalar tail (n_points % 4), normally empty for N = 1048576
            for (int p = n_items * 4; p < n_points; p++) {
                point_acc(pts[3 * p + 0], pts[3 * p + 1], pts[3 * p + 2], fs2, fc2, fm2);
            }
            int n_out = n_points - fc2;
            float loss_in  = (fc2   > 0) ? (0.001f * fs2 / (float)fc2) : 0.0f;
            float loss_out = (n_out > 0) ? fm2 : 0.0f;
            out[0] = loss_in + loss_out;
            g_done = 0;  // reset ticket so every graph replay starts clean
        }
    }
}

extern "C" void kernel_launch(void* const* d_in, const int* in_sizes, int n_in,
                              void* d_out, int out_size) {
    const float* pts = (const float*)d_in[0];
    int n_points = in_sizes[0] / 3;
    int n_items  = n_points / 4;                     // 4 points (48B) per item
    int n_blocks = (n_items + IPB - 1) / IPB;        // 512 for N = 1048576
    if (n_blocks > MAXBLK) n_blocks = MAXBLK;        // (N fixed; guard only)
    pbl_kernel<<<n_blocks, NTHR>>>((const char*)pts, pts, (float*)d_out,
                                   n_items, n_points, n_blocks);
}

// round 9
// speedup vs baseline: 1.1146x; 1.1146x over previous
#include <cuda_runtime.h>
#include <cuda_bf16.h>
#include <cstdint>

#define NTHR    256
#define IPB     256                  // items per block (1 item = 4 points = 48B)
#define TILE_B  (IPB * 48)           // 12288 bytes per block tile
#define MAXBLK  8192

// Per-block partials + completion ticket (module-scope device memory; no allocs).
__device__ float g_sum[MAXBLK];
__device__ int   g_cnt[MAXBLK];
__device__ float g_max[MAXBLK];
__device__ unsigned int g_done = 0;

__device__ __forceinline__ void point_acc(float x, float y, float z,
                                          float& acc_sum, int& acc_cnt, float& acc_max) {
    // Fold into positive octant: octahedron |x|+|y|+|z| <= 1 is sign-symmetric.
    float qx = fabsf(x), qy = fabsf(y), qz = fabsf(z);
    float s   = qx + qy + qz;
    float x2  = x * x, y2 = y * y, z2 = z * z;
    float dot = fmaf(x, x, fmaf(y, y, z * z));

    const float C = 0.57735026918962576f;           // fp32(1/sqrt(3))
    bool inside = (s * C - C) <= 1e-8f;             // same arithmetic as reference

    float mx  = fmaxf(qx, fmaxf(qy, qz));
    float mn  = fminf(qx, fminf(qy, qz));
    float mn2 = fminf(x2, fminf(y2, z2));

    float d2v = fmaf(-2.0f, mx, dot + 1.0f);        // nearest-vertex dist^2

    if (inside) {
        acc_sum += d2v;
        acc_cnt += 1;
    } else {
        // Exact distance^2 to simplex {q>=0, sum=1}: sorted threshold cascade.
        float t1      = s - 1.0f;
        float face_sq = (t1 * (1.0f / 3.0f)) * t1;
        bool  face_ok = (3.0f * mn >= t1);

        float tau2 = fmaf(0.5f, s - mn, -0.5f);
        float e    = fmaf(tau2 + tau2, tau2, mn2);
        bool  edge_ok = fmaf(-2.0f, mx, s + 1.0f) >= mn;

        float sq = edge_ok ? e : d2v;
        sq = face_ok ? face_sq : sq;
        acc_max = fmaxf(acc_max, sq);
    }
}

__device__ __forceinline__ uint32_t smem_u32(const void* p) {
    uint32_t a;
    asm("{ .reg .u64 t; cvta.to.shared.u64 t, %1; cvt.u32.u64 %0, t; }" : "=r"(a) : "l"(p));
    return a;
}

__device__ __forceinline__ void mbar_wait0(uint32_t mbar_a) {
    uint32_t done;
    asm volatile(
        "{\n\t.reg .pred p;\n\t"
        "mbarrier.try_wait.parity.acquire.cta.shared::cta.b64 p, [%1], 0;\n\t"
        "selp.b32 %0, 1, 0, p;\n\t}"
        : "=r"(done) : "r"(mbar_a) : "memory");
    while (!done) {
        asm volatile(
            "{\n\t.reg .pred p;\n\t"
            "mbarrier.try_wait.parity.acquire.cta.shared::cta.b64 p, [%1], 0, 0x989680;\n\t"
            "selp.b32 %0, 1, 0, p;\n\t}"
            : "=r"(done) : "r"(mbar_a) : "memory");
    }
}

// ---- Fused: one 12KB TMA tile per block (R6 shape) + ticket-based final reduce ----
__global__ void __launch_bounds__(NTHR)
pbl_kernel(const char* __restrict__ pts_bytes, const float* __restrict__ pts,
           float* __restrict__ out, int n_items, int n_points, int n_blocks) {
    __shared__ alignas(128) float4 tile[TILE_B / 16];   // 768 float4
    __shared__ alignas(8)  uint64_t mbar;
    __shared__ float s_sum[NTHR / 32];
    __shared__ int   s_cnt[NTHR / 32];
    __shared__ float s_max[NTHR / 32];
    __shared__ bool  s_is_last;

    const int tid  = threadIdx.x;
    const int lane = tid & 31;
    const int wid  = tid >> 5;

    const int first_item = blockIdx.x * IPB;
    const int blk_items  = min(IPB, n_items - first_item);   // may be <=0 (guard only)
    const uint32_t bytes = (blk_items > 0) ? (uint32_t)blk_items * 48u : 0u;

    const uint32_t mbar_a = smem_u32(&mbar);
    const uint32_t dst_a  = smem_u32(tile);

    if (tid == 0) {
        asm volatile("mbarrier.init.shared.b64 [%0], %1;" :: "r"(mbar_a), "r"(1u) : "memory");
    }
    __syncthreads();

    if (tid == 0) {
        asm volatile("mbarrier.arrive.expect_tx.shared.b64 _, [%0], %1;"
                     :: "r"(mbar_a), "r"(bytes) : "memory");
        if (bytes > 0) {
            const char* src = pts_bytes + (size_t)first_item * 48u;
            asm volatile(
                "cp.async.bulk.shared::cta.global.mbarrier::complete_tx::bytes [%0], [%1], %2, [%3];"
                :: "r"(dst_a), "l"(src), "r"(bytes), "r"(mbar_a) : "memory");
        }
    }

    mbar_wait0(mbar_a);

    float acc_sum = 0.0f;
    int   acc_cnt = 0;
    float acc_max = 0.0f;

    if (tid < blk_items) {
        // 3 x LDS.128 at 48B stride — bank-conflict-free
        float4 f0 = tile[3 * tid + 0];
        float4 f1 = tile[3 * tid + 1];
        float4 f2 = tile[3 * tid + 2];
        point_acc(f0.x, f0.y, f0.z, acc_sum, acc_cnt, acc_max);
        point_acc(f0.w, f1.x, f1.y, acc_sum, acc_cnt, acc_max);
        point_acc(f1.z, f1.w, f2.x, acc_sum, acc_cnt, acc_max);
        point_acc(f2.y, f2.z, f2.w, acc_sum, acc_cnt, acc_max);
    }

    // warp reduce
    #pragma unroll
    for (int o = 16; o > 0; o >>= 1) {
        acc_sum += __shfl_down_sync(0xffffffffu, acc_sum, o);
        acc_max  = fmaxf(acc_max, __shfl_down_sync(0xffffffffu, acc_max, o));
    }
    acc_cnt = __reduce_add_sync(0xffffffffu, acc_cnt);

    if (lane == 0) { s_sum[wid] = acc_sum; s_cnt[wid] = acc_cnt; s_max[wid] = acc_max; }
    __syncthreads();

    if (tid == 0) {
        float bs = 0.0f; int bc = 0; float bm = 0.0f;
        #pragma unroll
        for (int i = 0; i < NTHR / 32; i++) {
            bs += s_sum[i]; bc += s_cnt[i]; bm = fmaxf(bm, s_max[i]);
        }
        g_sum[blockIdx.x] = bs;
        g_cnt[blockIdx.x] = bc;
        g_max[blockIdx.x] = bm;
        __threadfence();
        unsigned int ticket = atomicAdd(&g_done, 1u);
        s_is_last = (ticket == (unsigned int)(n_blocks - 1));
    }
    __syncthreads();

    if (s_is_last) {
        __threadfence();  // acquire: all blocks' partials visible (L2-resident)
        float fs = 0.0f; int fc = 0; float fm = 0.0f;
        for (int i = tid; i < n_blocks; i += NTHR) {
            fs += g_sum[i]; fc += g_cnt[i]; fm = fmaxf(fm, g_max[i]);
        }
        #pragma unroll
        for (int o = 16; o > 0; o >>= 1) {
            fs += __shfl_down_sync(0xffffffffu, fs, o);
            fm  = fmaxf(fm, __shfl_down_sync(0xffffffffu, fm, o));
        }
        fc = __reduce_add_sync(0xffffffffu, fc);
        if (lane == 0) { s_sum[wid] = fs; s_cnt[wid] = fc; s_max[wid] = fm; }
        __syncthreads();
        if (tid == 0) {
            float fs2 = 0.0f; int fc2 = 0; float fm2 = 0.0f;
            #pragma unroll
            for (int i = 0; i < NTHR / 32; i++) {
                fs2 += s_sum[i]; fc2 += s_cnt[i]; fm2 = fmaxf(fm2, s_max[i]);
            }
            // scalar tail (n_points % 4), normally empty for N = 1048576
            for (int p = n_items * 4; p < n_points; p++) {
                point_acc(pts[3 * p + 0], pts[3 * p + 1], pts[3 * p + 2], fs2, fc2, fm2);
            }
            int n_out = n_points - fc2;
            float loss_in  = (fc2   > 0) ? (0.001f * fs2 / (float)fc2) : 0.0f;
            float loss_out = (n_out > 0) ? fm2 : 0.0f;
            out[0] = loss_in + loss_out;
            g_done = 0;  // reset ticket so every graph replay starts clean
        }
    }
}

extern "C" void kernel_launch(void* const* d_in, const int* in_sizes, int n_in,
                              void* d_out, int out_size) {
    const float* pts = (const float*)d_in[0];
    int n_points = in_sizes[0] / 3;
    int n_items  = n_points / 4;                     // 4 points (48B) per item
    int n_blocks = (n_items + IPB - 1) / IPB;        // 1024 for N = 1048576
    if (n_blocks > MAXBLK) n_blocks = MAXBLK;        // (N fixed; guard only)
    pbl_kernel<<<n_blocks, NTHR>>>((const char*)pts, pts, (float*)d_out,
                                   n_items, n_points, n_blocks);
}